// round 16
// baseline (speedup 1.0000x reference)
#include <cuda_runtime.h>
#include <math.h>
#include <float.h>

#define D_FEAT 256
#define BATCH  4096
#define NV     (D_FEAT / 4)   // 64 float4 per row

// Segment boundary table: g_offsets[s] = first row index with membership >= s.
__device__ int g_offsets[BATCH + 1];

// 4 membership values per thread (int4). membership is sorted.
__global__ void boundary_kernel(const int4* __restrict__ mem4, int n_atoms)
{
    int i4 = blockIdx.x * blockDim.x + threadIdx.x;
    int base = i4 * 4;
    if (base >= n_atoms) return;
    int4 v = mem4[i4];
    int vals[4] = {v.x, v.y, v.z, v.w};
    int prev = (base == 0) ? -1 : __ldg(((const int*)mem4) + base - 1);
    #pragma unroll
    for (int k = 0; k < 4; ++k) {
        int idx = base + k;
        if (idx >= n_atoms) break;
        int cur = vals[k];
        for (int s = prev + 1; s <= cur; ++s) g_offsets[s] = idx;
        if (idx == n_atoms - 1)
            for (int s = cur + 1; s <= BATCH; ++s) g_offsets[s] = n_atoms;
        prev = cur;
    }
}

#define ACC_SUM(acc, v)  do { acc.x += v.x; acc.y += v.y; acc.z += v.z; acc.w += v.w; } while (0)
#define ACC_MAX(acc, v)  do { acc.x = fmaxf(acc.x, v.x); acc.y = fmaxf(acc.y, v.y); \
                              acc.z = fmaxf(acc.z, v.z); acc.w = fmaxf(acc.w, v.w); } while (0)

// One CTA per segment. 256 threads: cg = t & 63 (float4 column),
// ro = t >> 6 (4 row groups, row stride 4). Unroll 12: twelve independent
// 16B streaming loads in flight per thread (192 B outstanding; regs ~76 ->
// occ 3/SM). Tests the bytes-in-flight model: occ3 x MLP12 = 144 KB/SM
// (> occ4 x MLP8 = 128 KB) AND the finer occ-3 slot quantization
// (4096/456 = 8.98 -> 99.8% ceiling).
__global__ __launch_bounds__(256, 3)
void graph_gather_kernel(const float4* __restrict__ feat,
                         float* __restrict__ out)
{
    const int seg   = blockIdx.x;
    const int start = g_offsets[seg];
    const int cnt   = g_offsets[seg + 1] - start;

    const int cg = threadIdx.x & (NV - 1);
    const int ro = threadIdx.x >> 6;

    const float4* __restrict__ p = feat + (size_t)start * NV + cg;

    float4 s0 = make_float4(0.f, 0.f, 0.f, 0.f);
    float4 s1 = s0;
    float4 m0 = make_float4(-INFINITY, -INFINITY, -INFINITY, -INFINITY);
    float4 m1 = m0;

    int r = ro;
    // 12 independent loads in flight per thread (192 B outstanding).
    for (; r + 44 < cnt; r += 48) {
        float4 a = __ldcs(&p[(size_t)(r     ) * NV]);
        float4 b = __ldcs(&p[(size_t)(r +  4) * NV]);
        float4 c = __ldcs(&p[(size_t)(r +  8) * NV]);
        float4 d = __ldcs(&p[(size_t)(r + 12) * NV]);
        float4 e = __ldcs(&p[(size_t)(r + 16) * NV]);
        float4 f = __ldcs(&p[(size_t)(r + 20) * NV]);
        float4 g = __ldcs(&p[(size_t)(r + 24) * NV]);
        float4 h = __ldcs(&p[(size_t)(r + 28) * NV]);
        float4 i = __ldcs(&p[(size_t)(r + 32) * NV]);
        float4 j = __ldcs(&p[(size_t)(r + 36) * NV]);
        float4 k = __ldcs(&p[(size_t)(r + 40) * NV]);
        float4 l = __ldcs(&p[(size_t)(r + 44) * NV]);

        s0.x += ((a.x + b.x) + (c.x + d.x)) + (e.x + f.x);
        s0.y += ((a.y + b.y) + (c.y + d.y)) + (e.y + f.y);
        s0.z += ((a.z + b.z) + (c.z + d.z)) + (e.z + f.z);
        s0.w += ((a.w + b.w) + (c.w + d.w)) + (e.w + f.w);
        s1.x += ((g.x + h.x) + (i.x + j.x)) + (k.x + l.x);
        s1.y += ((g.y + h.y) + (i.y + j.y)) + (k.y + l.y);
        s1.z += ((g.z + h.z) + (i.z + j.z)) + (k.z + l.z);
        s1.w += ((g.w + h.w) + (i.w + j.w)) + (k.w + l.w);

        m0.x = fmaxf(m0.x, fmaxf(fmaxf(fmaxf(a.x, b.x), fmaxf(c.x, d.x)), fmaxf(e.x, f.x)));
        m0.y = fmaxf(m0.y, fmaxf(fmaxf(fmaxf(a.y, b.y), fmaxf(c.y, d.y)), fmaxf(e.y, f.y)));
        m0.z = fmaxf(m0.z, fmaxf(fmaxf(fmaxf(a.z, b.z), fmaxf(c.z, d.z)), fmaxf(e.z, f.z)));
        m0.w = fmaxf(m0.w, fmaxf(fmaxf(fmaxf(a.w, b.w), fmaxf(c.w, d.w)), fmaxf(e.w, f.w)));
        m1.x = fmaxf(m1.x, fmaxf(fmaxf(fmaxf(g.x, h.x), fmaxf(i.x, j.x)), fmaxf(k.x, l.x)));
        m1.y = fmaxf(m1.y, fmaxf(fmaxf(fmaxf(g.y, h.y), fmaxf(i.y, j.y)), fmaxf(k.y, l.y)));
        m1.z = fmaxf(m1.z, fmaxf(fmaxf(fmaxf(g.z, h.z), fmaxf(i.z, j.z)), fmaxf(k.z, l.z)));
        m1.w = fmaxf(m1.w, fmaxf(fmaxf(fmaxf(g.w, h.w), fmaxf(i.w, j.w)), fmaxf(k.w, l.w)));
    }
    for (; r < cnt; r += 4) {
        float4 a = __ldcs(&p[(size_t)r * NV]);
        ACC_SUM(s0, a);
        ACC_MAX(m0, a);
    }

    float4 s, m;
    s.x = s0.x + s1.x; s.y = s0.y + s1.y;
    s.z = s0.z + s1.z; s.w = s0.w + s1.w;
    m.x = fmaxf(m0.x, m1.x); m.y = fmaxf(m0.y, m1.y);
    m.z = fmaxf(m0.z, m1.z); m.w = fmaxf(m0.w, m1.w);

    __shared__ float4 ssum[256];
    __shared__ float4 smax[256];
    ssum[threadIdx.x] = s;
    smax[threadIdx.x] = m;
    __syncthreads();

    // Threads 0-63 reduce sums, 64-127 reduce maxes (parallel halves).
    if (threadIdx.x < 128) {
        const int col    = threadIdx.x & (NV - 1);
        const bool ismax = threadIdx.x >= NV;
        const float4* buf = ismax ? smax : ssum;

        float4 v0 = buf[col],        v1 = buf[col + 64];
        float4 v2 = buf[col + 128],  v3 = buf[col + 192];

        float4 acc;
        if (ismax) {
            acc.x = fmaxf(fmaxf(v0.x, v1.x), fmaxf(v2.x, v3.x));
            acc.y = fmaxf(fmaxf(v0.y, v1.y), fmaxf(v2.y, v3.y));
            acc.z = fmaxf(fmaxf(v0.z, v1.z), fmaxf(v2.z, v3.z));
            acc.w = fmaxf(fmaxf(v0.w, v1.w), fmaxf(v2.w, v3.w));
        } else {
            acc.x = (v0.x + v1.x) + (v2.x + v3.x);
            acc.y = (v0.y + v1.y) + (v2.y + v3.y);
            acc.z = (v0.z + v1.z) + (v2.z + v3.z);
            acc.w = (v0.w + v1.w) + (v2.w + v3.w);
        }

        float4 t = make_float4(tanhf(acc.x), tanhf(acc.y),
                               tanhf(acc.z), tanhf(acc.w));

        float4* o = (float4*)out + (size_t)seg * (2 * NV)
                  + (ismax ? NV : 0) + col;
        __stcs(o, t);
    }
}

extern "C" void kernel_launch(void* const* d_in, const int* in_sizes, int n_in,
                              void* d_out, int out_size)
{
    const float* feat = (const float*)d_in[0];   // [N_ATOMS, 256] fp32
    const int*   mem  = (const int*)d_in[1];     // [N_ATOMS] int32, sorted
    float*       out  = (float*)d_out;           // [4096, 512] fp32

    const int n_atoms = in_sizes[1];

    int n4 = (n_atoms + 3) / 4;
    boundary_kernel<<<(n4 + 255) / 256, 256>>>((const int4*)mem, n_atoms);
    graph_gather_kernel<<<BATCH, 256>>>((const float4*)feat, out);
}

// round 17
// speedup vs baseline: 1.0484x; 1.0484x over previous
#include <cuda_runtime.h>
#include <math.h>
#include <float.h>

#define D_FEAT 256
#define BATCH  4096
#define NV     (D_FEAT / 4)   // 64 float4 per row

// Segment boundary table: g_offsets[s] = first row index with membership >= s.
__device__ int g_offsets[BATCH + 1];

// 4 membership values per thread (int4). membership is sorted.
__global__ void boundary_kernel(const int4* __restrict__ mem4, int n_atoms)
{
    int i4 = blockIdx.x * blockDim.x + threadIdx.x;
    int base = i4 * 4;
    if (base >= n_atoms) return;
    int4 v = mem4[i4];
    int vals[4] = {v.x, v.y, v.z, v.w};
    int prev = (base == 0) ? -1 : __ldg(((const int*)mem4) + base - 1);
    #pragma unroll
    for (int k = 0; k < 4; ++k) {
        int idx = base + k;
        if (idx >= n_atoms) break;
        int cur = vals[k];
        for (int s = prev + 1; s <= cur; ++s) g_offsets[s] = idx;
        if (idx == n_atoms - 1)
            for (int s = cur + 1; s <= BATCH; ++s) g_offsets[s] = n_atoms;
        prev = cur;
    }
}

#define ACC_SUM(acc, v)  do { acc.x += v.x; acc.y += v.y; acc.z += v.z; acc.w += v.w; } while (0)
#define ACC_MAX(acc, v)  do { acc.x = fmaxf(acc.x, v.x); acc.y = fmaxf(acc.y, v.y); \
                              acc.z = fmaxf(acc.z, v.z); acc.w = fmaxf(acc.w, v.w); } while (0)

// One CTA per segment. 256 threads: cg = t & 63 (float4 column),
// ro = t >> 6 (4 row groups, row stride 4). Unroll 8: eight independent
// 16B streaming loads in flight per thread (128 B outstanding).
// launch_bounds(256,3) pins the reg budget at 64 so ptxas keeps the full
// 8-deep MLP in SASS; 4 CTAs/SM physically fit and run — the measured
// optimum across the full design matrix:
//   occ5xMLP8 86.9% | occ4xMLP8 89.1% (this) | occ3xMLP8 86.5% | occ3xMLP12 86.5%
__global__ __launch_bounds__(256, 3)
void graph_gather_kernel(const float4* __restrict__ feat,
                         float* __restrict__ out)
{
    const int seg   = blockIdx.x;
    const int start = g_offsets[seg];
    const int cnt   = g_offsets[seg + 1] - start;

    const int cg = threadIdx.x & (NV - 1);
    const int ro = threadIdx.x >> 6;

    const float4* __restrict__ p = feat + (size_t)start * NV + cg;

    float4 s0 = make_float4(0.f, 0.f, 0.f, 0.f);
    float4 s1 = s0;
    float4 m0 = make_float4(-INFINITY, -INFINITY, -INFINITY, -INFINITY);
    float4 m1 = m0;

    int r = ro;
    for (; r + 28 < cnt; r += 32) {
        float4 a = __ldcs(&p[(size_t)(r     ) * NV]);
        float4 b = __ldcs(&p[(size_t)(r +  4) * NV]);
        float4 c = __ldcs(&p[(size_t)(r +  8) * NV]);
        float4 d = __ldcs(&p[(size_t)(r + 12) * NV]);
        float4 e = __ldcs(&p[(size_t)(r + 16) * NV]);
        float4 f = __ldcs(&p[(size_t)(r + 20) * NV]);
        float4 g = __ldcs(&p[(size_t)(r + 24) * NV]);
        float4 h = __ldcs(&p[(size_t)(r + 28) * NV]);

        s0.x += (a.x + b.x) + (c.x + d.x);
        s0.y += (a.y + b.y) + (c.y + d.y);
        s0.z += (a.z + b.z) + (c.z + d.z);
        s0.w += (a.w + b.w) + (c.w + d.w);
        s1.x += (e.x + f.x) + (g.x + h.x);
        s1.y += (e.y + f.y) + (g.y + h.y);
        s1.z += (e.z + f.z) + (g.z + h.z);
        s1.w += (e.w + f.w) + (g.w + h.w);

        m0.x = fmaxf(m0.x, fmaxf(fmaxf(a.x, b.x), fmaxf(c.x, d.x)));
        m0.y = fmaxf(m0.y, fmaxf(fmaxf(a.y, b.y), fmaxf(c.y, d.y)));
        m0.z = fmaxf(m0.z, fmaxf(fmaxf(a.z, b.z), fmaxf(c.z, d.z)));
        m0.w = fmaxf(m0.w, fmaxf(fmaxf(a.w, b.w), fmaxf(c.w, d.w)));
        m1.x = fmaxf(m1.x, fmaxf(fmaxf(e.x, f.x), fmaxf(g.x, h.x)));
        m1.y = fmaxf(m1.y, fmaxf(fmaxf(e.y, f.y), fmaxf(g.y, h.y)));
        m1.z = fmaxf(m1.z, fmaxf(fmaxf(e.z, f.z), fmaxf(g.z, h.z)));
        m1.w = fmaxf(m1.w, fmaxf(fmaxf(e.w, f.w), fmaxf(g.w, h.w)));
    }
    for (; r < cnt; r += 4) {
        float4 a = __ldcs(&p[(size_t)r * NV]);
        ACC_SUM(s0, a);
        ACC_MAX(m0, a);
    }

    float4 s, m;
    s.x = s0.x + s1.x; s.y = s0.y + s1.y;
    s.z = s0.z + s1.z; s.w = s0.w + s1.w;
    m.x = fmaxf(m0.x, m1.x); m.y = fmaxf(m0.y, m1.y);
    m.z = fmaxf(m0.z, m1.z); m.w = fmaxf(m0.w, m1.w);

    __shared__ float4 ssum[256];
    __shared__ float4 smax[256];
    ssum[threadIdx.x] = s;
    smax[threadIdx.x] = m;
    __syncthreads();

    // Threads 0-63 reduce sums, 64-127 reduce maxes (parallel halves).
    if (threadIdx.x < 128) {
        const int col    = threadIdx.x & (NV - 1);
        const bool ismax = threadIdx.x >= NV;
        const float4* buf = ismax ? smax : ssum;

        float4 v0 = buf[col],        v1 = buf[col + 64];
        float4 v2 = buf[col + 128],  v3 = buf[col + 192];

        float4 acc;
        if (ismax) {
            acc.x = fmaxf(fmaxf(v0.x, v1.x), fmaxf(v2.x, v3.x));
            acc.y = fmaxf(fmaxf(v0.y, v1.y), fmaxf(v2.y, v3.y));
            acc.z = fmaxf(fmaxf(v0.z, v1.z), fmaxf(v2.z, v3.z));
            acc.w = fmaxf(fmaxf(v0.w, v1.w), fmaxf(v2.w, v3.w));
        } else {
            acc.x = (v0.x + v1.x) + (v2.x + v3.x);
            acc.y = (v0.y + v1.y) + (v2.y + v3.y);
            acc.z = (v0.z + v1.z) + (v2.z + v3.z);
            acc.w = (v0.w + v1.w) + (v2.w + v3.w);
        }

        float4 t = make_float4(tanhf(acc.x), tanhf(acc.y),
                               tanhf(acc.z), tanhf(acc.w));

        float4* o = (float4*)out + (size_t)seg * (2 * NV)
                  + (ismax ? NV : 0) + col;
        __stcs(o, t);
    }
}

extern "C" void kernel_launch(void* const* d_in, const int* in_sizes, int n_in,
                              void* d_out, int out_size)
{
    const float* feat = (const float*)d_in[0];   // [N_ATOMS, 256] fp32
    const int*   mem  = (const int*)d_in[1];     // [N_ATOMS] int32, sorted
    float*       out  = (float*)d_out;           // [4096, 512] fp32

    const int n_atoms = in_sizes[1];

    int n4 = (n_atoms + 3) / 4;
    boundary_kernel<<<(n4 + 255) / 256, 256>>>((const int4*)mem, n_atoms);
    graph_gather_kernel<<<BATCH, 256>>>((const float4*)feat, out);
}